// round 1
// baseline (speedup 1.0000x reference)
#include <cuda_runtime.h>

// Problem constants (from reference_code)
#define Bn      64
#define Cn      3
#define h_img   416
#define w_img   416
#define H_out   608
#define W_out   608
#define ROW_OFF 85
#define COL_OFF 80

#define W4   (W_out / 4)   // 152 float4 per output row
#define w4   (w_img / 4)   // 104 float4 per img row
#define X4_OFF (COL_OFF / 4) // 20  (COL_OFF divisible by 4 -> aligned)

__global__ void __launch_bounds__(256)
composite_kernel(const float4* __restrict__ img,   // [B,3,h,w] as float4
                 const float4* __restrict__ ref,   // [1,3,H,W] as float4
                 float4* __restrict__ out)         // [B,3,H,W] as float4
{
    const int total = Bn * H_out * W4;
    int idx = blockIdx.x * blockDim.x + threadIdx.x;
    if (idx >= total) return;

    int x4 = idx % W4;
    int t  = idx / W4;
    int y  = t % H_out;
    int b  = t / H_out;

    // Reference pixels for all 3 channels (small tensor, L2-resident; default cache)
    const float4 r0 = ref[(size_t)(0 * H_out + y) * W4 + x4];
    const float4 r1 = ref[(size_t)(1 * H_out + y) * W4 + x4];
    const float4 r2 = ref[(size_t)(2 * H_out + y) * W4 + x4];

    float4 o0 = r0, o1 = r1, o2 = r2;

    const int ry  = y  - ROW_OFF;
    const int rx4 = x4 - X4_OFF;
    if (ry >= 0 && ry < h_img && rx4 >= 0 && rx4 < w4) {
        const size_t ibase = (size_t)b * 3 * h_img * w4;
        // Channel 2 is both the mask and the channel-2 payload.
        const float4 m  = __ldcs(&img[ibase + (size_t)(2 * h_img + ry) * w4 + rx4]);
        const float4 i0 = __ldcs(&img[ibase + (size_t)(0 * h_img + ry) * w4 + rx4]);
        const float4 i1 = __ldcs(&img[ibase + (size_t)(1 * h_img + ry) * w4 + rx4]);

        if (m.x != 0.0f) { o0.x = i0.x; o1.x = i1.x; o2.x = m.x; }
        if (m.y != 0.0f) { o0.y = i0.y; o1.y = i1.y; o2.y = m.y; }
        if (m.z != 0.0f) { o0.z = i0.z; o1.z = i1.z; o2.z = m.z; }
        if (m.w != 0.0f) { o0.w = i0.w; o1.w = i1.w; o2.w = m.w; }
    }

    const size_t obase = (size_t)b * 3 * H_out * W4;
    __stcs(&out[obase + (size_t)(0 * H_out + y) * W4 + x4], o0);
    __stcs(&out[obase + (size_t)(1 * H_out + y) * W4 + x4], o1);
    __stcs(&out[obase + (size_t)(2 * H_out + y) * W4 + x4], o2);
}

extern "C" void kernel_launch(void* const* d_in, const int* in_sizes, int n_in,
                              void* d_out, int out_size)
{
    const float4* img = (const float4*)d_in[0];   // [64,3,416,416] f32
    const float4* ref = (const float4*)d_in[1];   // [1,3,608,608]  f32
    float4* out = (float4*)d_out;                 // [64,3,608,608] f32

    const int total = Bn * H_out * W4;            // 5,910,528 threads
    const int threads = 256;
    const int blocks = (total + threads - 1) / threads;
    composite_kernel<<<blocks, threads>>>(img, ref, out);
}